// round 3
// baseline (speedup 1.0000x reference)
#include <cuda_runtime.h>
#include <cstdint>

// ---------------------------------------------------------------------------
// SRNN forward:
//   inp_cur[t,b,r] = sum_i x[b,i,t] * w_inp[r,i]
//   per step t=0..998:
//     v1 = ALPHA*v + z @ w_rec_eff.T + inp_cur[t] - z*THR   (w_rec diag zeroed)
//     z1 = (v1 > THR);  vo1 = KAPPA*vo + z1 @ w_out.T
//   out[0]=0, out[t+1]=vo1.  out shape (1000,128,32) f32
// ---------------------------------------------------------------------------

#define N_B      128
#define INP_DIM  256
#define N_T      1000
#define N_REC    512
#define OUT_DIM  32
#define N_STEPS  999

#define ALPHA 0.9512294245007140f
#define KAPPA 0.9512294245007140f
#define THR   0.6f

#define ROWS  (N_STEPS * N_B)      // 127872 = 864 * 148
#define ROWS_PER_CTA 864
#define CHUNK 16

// ---- scratch (__device__ globals; no allocation) ----
__device__ float    g_inp[(size_t)N_B * N_STEPS * N_REC];   // (b,t,r), 262 MB
__device__ unsigned g_masks[(size_t)ROWS * 8];              // 256-bit mask per (t,b)
__device__ float    g_wrecT[N_REC * N_REC];                 // [s][r], diag 0
__device__ float    g_woutT[N_REC * OUT_DIM];               // [r][o]
__device__ float    g_winpT[INP_DIM * N_REC];               // [i][r]

// ---------------------------------------------------------------------------
// Kernel 1: pack x (b,i,t) into per-(t,b) 256-bit masks. Coalesced over t.
// ---------------------------------------------------------------------------
__global__ void k_masks(const float* __restrict__ x) {
    int b = blockIdx.x;
    int t = blockIdx.y * 256 + threadIdx.x;
    if (t >= N_STEPS) return;

    unsigned m[8] = {0,0,0,0,0,0,0,0};
    const float* xp = x + (size_t)b * INP_DIM * N_T + t;
#pragma unroll
    for (int i = 0; i < INP_DIM; i++) {
        if (xp[(size_t)i * N_T] > 0.5f) m[i >> 5] |= (1u << (i & 31));
    }
    unsigned* dst = g_masks + ((size_t)t * N_B + b) * 8;
#pragma unroll
    for (int w = 0; w < 8; w++) dst[w] = m[w];
}

// ---------------------------------------------------------------------------
// Kernel 2: weight transposes.
// ---------------------------------------------------------------------------
__global__ void k_prep(const float* __restrict__ w_rec,
                       const float* __restrict__ w_out,
                       const float* __restrict__ w_inp) {
    int stride = gridDim.x * blockDim.x;
    int idx0 = blockIdx.x * blockDim.x + threadIdx.x;

    for (int i = idx0; i < N_REC * N_REC; i += stride) {
        int s = i >> 9, r = i & (N_REC - 1);
        float v = w_rec[(size_t)r * N_REC + s];
        g_wrecT[i] = (r == s) ? 0.0f : v;
    }
    for (int i = idx0; i < N_REC * OUT_DIM; i += stride) {
        int r = i >> 5, o = i & 31;
        g_woutT[i] = w_out[(size_t)o * N_REC + r];
    }
    for (int i = idx0; i < INP_DIM * N_REC; i += stride) {
        int ii = i >> 9, r = i & (N_REC - 1);
        g_winpT[i] = w_inp[(size_t)r * INP_DIM + ii];
    }
}

// ---------------------------------------------------------------------------
// Kernel 3: sparse input GEMM — warp-per-row, no barriers, 64-r slices so
// 3 CTAs/SM (64 KB smem each) hide the ffs-chain latency.
//   grid (8 rec-slices, 148 chunks), 256 threads (8 warps).
// ---------------------------------------------------------------------------
#define K_INP_SMEM (INP_DIM * 64 * 4)   // 64 KB

__global__ void __launch_bounds__(256) k_inp_kernel() {
    extern __shared__ float w_sh[];               // [256 i][64 r]

    int slice = blockIdx.x;                       // 0..7
    int chunk = blockIdx.y;                       // 0..147
    int tid   = threadIdx.x;
    int wid   = tid >> 5;
    int lane  = tid & 31;
    int r0    = slice * 64;

    for (int idx = tid; idx < INP_DIM * 64; idx += 256) {
        int i = idx >> 6, rr = idx & 63;
        w_sh[idx] = g_winpT[(size_t)i * N_REC + r0 + rr];
    }
    __syncthreads();

    int rowbase = chunk * ROWS_PER_CTA;
    int row0 = rowbase + wid;
    unsigned mw = (lane < 8) ? __ldg(&g_masks[(size_t)row0 * 8 + lane]) : 0u;

    for (int j = 0; j < ROWS_PER_CTA / 8; j++) {
        int row = rowbase + j * 8 + wid;
        unsigned curw = mw;
        if (j < ROWS_PER_CTA / 8 - 1)
            mw = (lane < 8) ? __ldg(&g_masks[(size_t)(row + 8) * 8 + lane]) : 0u;

        float2 acc = make_float2(0.f, 0.f);
#pragma unroll
        for (int w = 0; w < 8; w++) {
            unsigned m = __shfl_sync(0xffffffffu, curw, w);
            int ibase = w * 32;
            while (m) {
                int i = ibase + __ffs((int)m) - 1;
                m &= (m - 1);
                float2 wv = *(const float2*)&w_sh[(i << 6) + (lane << 1)];
                acc.x += wv.x; acc.y += wv.y;
            }
        }
        int t = row >> 7, bb = row & 127;         // row = t*128 + b
        float2* dst = (float2*)(g_inp + ((size_t)bb * N_STEPS + t) * N_REC + r0) + lane;
        *dst = acc;
    }
}

// ---------------------------------------------------------------------------
// Kernel 4: chunked speculative scan. 1 CTA/batch, 512 threads (neuron/thread).
//   16 steps per barrier; events (spikes, ~9 per batch) trigger replay.
// ---------------------------------------------------------------------------
__device__ __forceinline__ float gather_rec(const unsigned* mask, int r) {
    float acc = 0.f;
#pragma unroll 4
    for (int wd = 0; wd < 16; wd++) {
        unsigned m = mask[wd];
        while (m) {
            int l = __ffs((int)m) - 1;
            m &= (m - 1);
            int s = (wd << 5) + l;
            acc += g_wrecT[((size_t)s << 9) + r];
        }
    }
    return acc;
}

__device__ __forceinline__ float gather_out(const unsigned* mask, int o) {
    float acc = 0.f;
#pragma unroll 4
    for (int wd = 0; wd < 16; wd++) {
        unsigned m = mask[wd];
        while (m) {
            int l = __ffs((int)m) - 1;
            m &= (m - 1);
            int s = (wd << 5) + l;
            acc += g_woutT[(s << 5) + o];
        }
    }
    return acc;
}

__global__ void __launch_bounds__(512) k_scan(float* __restrict__ out) {
    __shared__ unsigned smask[2][16];   // spike identity masks (ping-pong)
    __shared__ unsigned sor[2][16];     // per-warp OR of spike bits (ping-pong)

    int b    = blockIdx.x;
    int tid  = threadIdx.x;
    int wid  = tid >> 5;
    int lane = tid & 31;

    const float* inp = g_inp + (size_t)b * N_STEPS * N_REC + tid;

    float v = 0.f, zprev = 0.f, vo = 0.f;
    int prev_any = 0, pm = 0, q = 0;

    if (tid < OUT_DIM) out[b * OUT_DIM + tid] = 0.f;      // out[0] = 0

    float buf[CHUNK], nbuf[CHUNK];
    int t = 0;
#pragma unroll
    for (int c = 0; c < CHUNK; c++) {
        int tt = c < N_STEPS ? c : N_STEPS - 1;
        buf[c] = __ldg(inp + (size_t)tt * N_REC);
    }

    while (t < N_STEPS) {
        int C = N_STEPS - t; C = C < CHUNK ? C : CHUNK;

        // prefetch next chunk (fast-path assumption)
#pragma unroll
        for (int c = 0; c < CHUNK; c++) {
            int tt = t + CHUNK + c; tt = tt < N_STEPS ? tt : N_STEPS - 1;
            nbuf[c] = __ldg(inp + (size_t)tt * N_REC);
        }

        // speculative pass: own-spike dynamics only
        float v_s = v, z_s = zprev;
        unsigned bits = 0;
#pragma unroll
        for (int c = 0; c < CHUNK; c++) {
            if (c < C) {
                float vn = fmaf(ALPHA, v_s, buf[c]) - z_s * THR;
                if (c == 0 && prev_any) vn += gather_rec(smask[pm], tid);
                int z = vn > THR;
                bits |= (unsigned)z << c;
                v_s = vn; z_s = z ? 1.f : 0.f;
            }
        }

        // one barrier: block-wide OR of spike bits
        unsigned wor = __reduce_or_sync(0xffffffffu, bits);
        if (lane == 0) sor[q][wid] = wor;
        __syncthreads();
        unsigned allbits = 0;
#pragma unroll
        for (int wd = 0; wd < 16; wd++) allbits |= sor[q][wd];
        q ^= 1;

        if (allbits == 0) {
            // commit whole chunk; no spikes anywhere -> vo pure decay (exact)
            v = v_s; zprev = 0.f;
            if (wid == 0) {
#pragma unroll
                for (int c = 0; c < CHUNK; c++) {
                    if (c < C) {
                        vo = KAPPA * vo;
                        out[(size_t)(t + c + 1) * (N_B * OUT_DIM) + b * OUT_DIM + lane] = vo;
                    }
                }
            }
            prev_any = 0;
            t += C;
#pragma unroll
            for (int c = 0; c < CHUNK; c++) buf[c] = nbuf[c];
        } else {
            int cs = __ffs((int)allbits) - 1;   // earliest spike step (valid)
            // identities of spikers at step t+cs
            int myz = (bits >> cs) & 1;
            unsigned bal = __ballot_sync(0xffffffffu, myz);
            int np = pm ^ 1;
            if (lane == 0) smask[np][wid] = bal;
            __syncthreads();

            // replay steps c = 0..cs (valid: no foreign spikes before cs)
            float vr = v, zr = zprev;
#pragma unroll
            for (int c = 0; c < CHUNK; c++) {
                if (c <= cs) {
                    float vn = fmaf(ALPHA, vr, buf[c]) - zr * THR;
                    if (c == 0 && prev_any) vn += gather_rec(smask[pm], tid);
                    int z = vn > THR;
                    vr = vn; zr = z ? 1.f : 0.f;
                }
            }
            v = vr; zprev = zr;

            if (wid == 0) {
#pragma unroll
                for (int c = 0; c < CHUNK; c++) {
                    if (c < cs) {
                        vo = KAPPA * vo;
                        out[(size_t)(t + c + 1) * (N_B * OUT_DIM) + b * OUT_DIM + lane] = vo;
                    }
                }
                vo = KAPPA * vo + gather_out(smask[np], lane);   // step t+cs has spikes
                out[(size_t)(t + cs + 1) * (N_B * OUT_DIM) + b * OUT_DIM + lane] = vo;
            }
            prev_any = 1; pm = np;
            t += cs + 1;
            // reload buffer for realigned t (mostly L1/L2 hits)
#pragma unroll
            for (int c = 0; c < CHUNK; c++) {
                int tt = t + c; tt = tt < N_STEPS ? tt : N_STEPS - 1;
                buf[c] = __ldg(inp + (size_t)tt * N_REC);
            }
        }
    }
}

// ---------------------------------------------------------------------------
extern "C" void kernel_launch(void* const* d_in, const int* in_sizes, int n_in,
                              void* d_out, int out_size) {
    const float* x     = (const float*)d_in[0];
    const float* w_inp = (const float*)d_in[1];
    const float* w_rec = (const float*)d_in[2];
    const float* w_out = (const float*)d_in[3];
    float* out = (float*)d_out;

    cudaFuncSetAttribute(k_inp_kernel,
                         cudaFuncAttributeMaxDynamicSharedMemorySize, K_INP_SMEM);

    k_masks<<<dim3(N_B, 4), 256>>>(x);
    k_prep<<<256, 256>>>(w_rec, w_out, w_inp);
    k_inp_kernel<<<dim3(8, 148), 256, K_INP_SMEM>>>();
    k_scan<<<N_B, 512>>>(out);
}